// round 1
// baseline (speedup 1.0000x reference)
#include <cuda_runtime.h>
#include <cuda_bf16.h>
#include <cstdint>

#define INV_SQRT3 0.57735026918962576451f
#define INV_SQRT2 0.70710678118654752440f
#define LN_EPS 1e-5f

// ---------------------------------------------------------------------------
// vector red.global helpers (sm_90+ PTX)
// ---------------------------------------------------------------------------
__device__ __forceinline__ void red_add_v4(float* p, float a, float b, float c, float d) {
    asm volatile("red.global.add.v4.f32 [%0], {%1,%2,%3,%4};"
                 :: "l"(p), "f"(a), "f"(b), "f"(c), "f"(d) : "memory");
}
__device__ __forceinline__ void red_add_v2(float* p, float a, float b) {
    asm volatile("red.global.add.v2.f32 [%0], {%1,%2};"
                 :: "l"(p), "f"(a), "f"(b) : "memory");
}

__device__ __forceinline__ float warp_sum(float v) {
    v += __shfl_xor_sync(0xffffffffu, v, 16);
    v += __shfl_xor_sync(0xffffffffu, v, 8);
    v += __shfl_xor_sync(0xffffffffu, v, 4);
    v += __shfl_xor_sync(0xffffffffu, v, 2);
    v += __shfl_xor_sync(0xffffffffu, v, 1);
    return v;
}

// ---------------------------------------------------------------------------
// Kernel 0: zero the accumulator (d_out used as agg buffer)
// ---------------------------------------------------------------------------
__global__ void zero_kernel(float4* __restrict__ p, int n4) {
    int i = blockIdx.x * blockDim.x + threadIdx.x;
    int stride = gridDim.x * blockDim.x;
    float4 z = make_float4(0.f, 0.f, 0.f, 0.f);
    for (; i < n4; i += stride) p[i] = z;
}

// ---------------------------------------------------------------------------
// Kernel 1: fused depthwise TP + tp_bias + scatter-add (warp per edge)
//
// Output layout per row (960 floats):
//   [  0,128) out0a : w0[u]*xs[u]*ys + bias[u]
//   [128,192) out0b : w3[v]*(xv[v].yv)/sqrt3 + bias[128+v]
//   [192,576) out1a : (w1[u]*xs[u]) * yv[d]         (u*3+d)
//   [576,768) out1b : (w2[v]*ys) * xv[v][d]
//   [768,960) out1c : w4[v]*cross(xv[v],yv)[d]/sqrt2
//
// lane L handles scalar channels u = 4L..4L+3 and vector channels v = 2L, 2L+1
// ---------------------------------------------------------------------------
__global__ void __launch_bounds__(256) tp_scatter_kernel(
    const float* __restrict__ node_feat,   // (N, 320)
    const float* __restrict__ edge_sh,     // (E, 4)
    const float* __restrict__ edge_weight, // (E, 448)
    const float* __restrict__ tp_bias,     // (192,)
    const int*   __restrict__ edge_src,
    const int*   __restrict__ edge_dst,
    float*       __restrict__ out,         // (N, 960) accumulator
    int n_edges)
{
    int warp = (blockIdx.x * blockDim.x + threadIdx.x) >> 5;
    int lane = threadIdx.x & 31;
    if (warp >= n_edges) return;
    const int e = warp;

    const int s = __ldg(edge_src + e);
    const int d = __ldg(edge_dst + e);

    const float4 shv = *reinterpret_cast<const float4*>(edge_sh + 4u * e);
    const float ys = shv.x, yv0 = shv.y, yv1 = shv.z, yv2 = shv.w;

    const float* xrow = node_feat + (size_t)s * 320u;
    const float* wrow = edge_weight + (size_t)e * 448u;
    float* orow = out + (size_t)d * 960u;

    // ---- scalar part: u = 4*lane .. 4*lane+3 -------------------------------
    const float4 xs = *reinterpret_cast<const float4*>(xrow + 4 * lane);
    const float4 w0 = *reinterpret_cast<const float4*>(wrow + 4 * lane);
    const float4 w1 = *reinterpret_cast<const float4*>(wrow + 128 + 4 * lane);
    const float4 b0 = *reinterpret_cast<const float4*>(tp_bias + 4 * lane);

    // out0a + bias
    red_add_v4(orow + 4 * lane,
               w0.x * xs.x * ys + b0.x,
               w0.y * xs.y * ys + b0.y,
               w0.z * xs.z * ys + b0.z,
               w0.w * xs.w * ys + b0.w);

    // out1a: t_u * yv[d], 12 contiguous floats at 192 + 12*lane
    const float t0 = w1.x * xs.x, t1 = w1.y * xs.y, t2 = w1.z * xs.z, t3 = w1.w * xs.w;
    float* p1a = orow + 192 + 12 * lane;
    red_add_v4(p1a,     t0 * yv0, t0 * yv1, t0 * yv2, t1 * yv0);
    red_add_v4(p1a + 4, t1 * yv1, t1 * yv2, t2 * yv0, t2 * yv1);
    red_add_v4(p1a + 8, t2 * yv2, t3 * yv0, t3 * yv1, t3 * yv2);

    // ---- vector part: v = 2*lane, 2*lane+1 ---------------------------------
    const float2 w2 = *reinterpret_cast<const float2*>(wrow + 256 + 2 * lane);
    const float2 w3 = *reinterpret_cast<const float2*>(wrow + 320 + 2 * lane);
    const float2 w4 = *reinterpret_cast<const float2*>(wrow + 384 + 2 * lane);
    const float2 bb = *reinterpret_cast<const float2*>(tp_bias + 128 + 2 * lane);

    const float2 p0 = *reinterpret_cast<const float2*>(xrow + 128 + 6 * lane);
    const float2 p1 = *reinterpret_cast<const float2*>(xrow + 128 + 6 * lane + 2);
    const float2 p2 = *reinterpret_cast<const float2*>(xrow + 128 + 6 * lane + 4);
    // xv[v0] = (p0.x, p0.y, p1.x) ; xv[v1] = (p1.y, p2.x, p2.y)

    // out0b: w3 * dot(xv, yv) / sqrt3 + bias
    const float d0 = p0.x * yv0 + p0.y * yv1 + p1.x * yv2;
    const float d1 = p1.y * yv0 + p2.x * yv1 + p2.y * yv2;
    red_add_v2(orow + 128 + 2 * lane,
               w3.x * d0 * INV_SQRT3 + bb.x,
               w3.y * d1 * INV_SQRT3 + bb.y);

    // out1b: (w2*ys) * xv
    const float c0 = w2.x * ys, c1 = w2.y * ys;
    float* p1b = orow + 576 + 6 * lane;
    red_add_v2(p1b,     c0 * p0.x, c0 * p0.y);
    red_add_v2(p1b + 2, c0 * p1.x, c1 * p1.y);
    red_add_v2(p1b + 4, c1 * p2.x, c1 * p2.y);

    // out1c: w4 * cross(xv, yv) / sqrt2
    // cross(a,b) = (a1*b2 - a2*b1, a2*b0 - a0*b2, a0*b1 - a1*b0)
    const float k0 = w4.x * INV_SQRT2, k1 = w4.y * INV_SQRT2;
    const float cr0 = p0.y * yv2 - p1.x * yv1;
    const float cr1 = p1.x * yv0 - p0.x * yv2;
    const float cr2 = p0.x * yv1 - p0.y * yv0;
    const float cr3 = p2.x * yv2 - p2.y * yv1;
    const float cr4 = p2.y * yv0 - p1.y * yv2;
    const float cr5 = p1.y * yv1 - p2.x * yv0;
    float* p1c = orow + 768 + 6 * lane;
    red_add_v2(p1c,     k0 * cr0, k0 * cr1);
    red_add_v2(p1c + 2, k0 * cr2, k1 * cr3);
    red_add_v2(p1c + 4, k1 * cr4, k1 * cr5);
}

// ---------------------------------------------------------------------------
// Kernel 2: equivariant LayerNorm, in place. Warp per node.
// fields: (128,l0)[0,128) (64,l0)[128,192) (128,l1)[192,576)
//         (64,l1)[576,768) (64,l1)[768,960)
// weights: [0:128][128:192][192:320][320:384][384:448], biases [0:128][128:192]
// ---------------------------------------------------------------------------
__global__ void __launch_bounds__(256) ln_kernel(
    float* __restrict__ out,
    const float* __restrict__ lnw,
    const float* __restrict__ lnb,
    int n_nodes)
{
    int warp = (blockIdx.x * blockDim.x + threadIdx.x) >> 5;
    int lane = threadIdx.x & 31;
    if (warp >= n_nodes) return;

    float* row = out + (size_t)warp * 960u;

    // ---- loads -------------------------------------------------------------
    float4 f0  = *reinterpret_cast<float4*>(row + 4 * lane);            // field0
    float2 f1  = *reinterpret_cast<float2*>(row + 128 + 2 * lane);      // field1
    float4 g2a = *reinterpret_cast<float4*>(row + 192 + 12 * lane);     // field2
    float4 g2b = *reinterpret_cast<float4*>(row + 192 + 12 * lane + 4);
    float4 g2c = *reinterpret_cast<float4*>(row + 192 + 12 * lane + 8);
    float2 g3a = *reinterpret_cast<float2*>(row + 576 + 6 * lane);      // field3
    float2 g3b = *reinterpret_cast<float2*>(row + 576 + 6 * lane + 2);
    float2 g3c = *reinterpret_cast<float2*>(row + 576 + 6 * lane + 4);
    float2 g4a = *reinterpret_cast<float2*>(row + 768 + 6 * lane);      // field4
    float2 g4b = *reinterpret_cast<float2*>(row + 768 + 6 * lane + 2);
    float2 g4c = *reinterpret_cast<float2*>(row + 768 + 6 * lane + 4);

    // ---- per-lane partial sums ----------------------------------------------
    float s0 = f0.x + f0.y + f0.z + f0.w;
    float q0 = f0.x * f0.x + f0.y * f0.y + f0.z * f0.z + f0.w * f0.w;
    float s1 = f1.x + f1.y;
    float q1 = f1.x * f1.x + f1.y * f1.y;
    float q2 = g2a.x*g2a.x + g2a.y*g2a.y + g2a.z*g2a.z + g2a.w*g2a.w
             + g2b.x*g2b.x + g2b.y*g2b.y + g2b.z*g2b.z + g2b.w*g2b.w
             + g2c.x*g2c.x + g2c.y*g2c.y + g2c.z*g2c.z + g2c.w*g2c.w;
    float q3 = g3a.x*g3a.x + g3a.y*g3a.y + g3b.x*g3b.x + g3b.y*g3b.y
             + g3c.x*g3c.x + g3c.y*g3c.y;
    float q4 = g4a.x*g4a.x + g4a.y*g4a.y + g4b.x*g4b.x + g4b.y*g4b.y
             + g4c.x*g4c.x + g4c.y*g4c.y;

    s0 = warp_sum(s0); q0 = warp_sum(q0);
    s1 = warp_sum(s1); q1 = warp_sum(q1);
    q2 = warp_sum(q2); q3 = warp_sum(q3); q4 = warp_sum(q4);

    const float mu0 = s0 * (1.f / 128.f);
    const float r0  = rsqrtf(fmaxf(q0 * (1.f / 128.f) - mu0 * mu0, 0.f) + LN_EPS);
    const float mu1 = s1 * (1.f / 64.f);
    const float r1  = rsqrtf(fmaxf(q1 * (1.f / 64.f) - mu1 * mu1, 0.f) + LN_EPS);
    const float r2  = rsqrtf(q2 * (1.f / 384.f) + LN_EPS);
    const float r3  = rsqrtf(q3 * (1.f / 192.f) + LN_EPS);
    const float r4  = rsqrtf(q4 * (1.f / 192.f) + LN_EPS);

    // ---- apply ---------------------------------------------------------------
    {   // field0: (f - mu)*r0*w + b
        const float4 wv = *reinterpret_cast<const float4*>(lnw + 4 * lane);
        const float4 bv = *reinterpret_cast<const float4*>(lnb + 4 * lane);
        f0.x = (f0.x - mu0) * r0 * wv.x + bv.x;
        f0.y = (f0.y - mu0) * r0 * wv.y + bv.y;
        f0.z = (f0.z - mu0) * r0 * wv.z + bv.z;
        f0.w = (f0.w - mu0) * r0 * wv.w + bv.w;
        *reinterpret_cast<float4*>(row + 4 * lane) = f0;
    }
    {   // field1
        const float2 wv = *reinterpret_cast<const float2*>(lnw + 128 + 2 * lane);
        const float2 bv = *reinterpret_cast<const float2*>(lnb + 128 + 2 * lane);
        f1.x = (f1.x - mu1) * r1 * wv.x + bv.x;
        f1.y = (f1.y - mu1) * r1 * wv.y + bv.y;
        *reinterpret_cast<float2*>(row + 128 + 2 * lane) = f1;
    }
    {   // field2: u = 4*lane + {0..3}, scale per u
        const float4 wv = *reinterpret_cast<const float4*>(lnw + 192 + 4 * lane);
        const float a = wv.x * r2, b = wv.y * r2, c = wv.z * r2, d = wv.w * r2;
        g2a.x *= a; g2a.y *= a; g2a.z *= a; g2a.w *= b;
        g2b.x *= b; g2b.y *= b; g2b.z *= c; g2b.w *= c;
        g2c.x *= c; g2c.y *= d; g2c.z *= d; g2c.w *= d;
        *reinterpret_cast<float4*>(row + 192 + 12 * lane)     = g2a;
        *reinterpret_cast<float4*>(row + 192 + 12 * lane + 4) = g2b;
        *reinterpret_cast<float4*>(row + 192 + 12 * lane + 8) = g2c;
    }
    {   // field3: u = 2*lane + {0,1}
        const float2 wv = *reinterpret_cast<const float2*>(lnw + 320 + 2 * lane);
        const float a = wv.x * r3, b = wv.y * r3;
        g3a.x *= a; g3a.y *= a; g3b.x *= a; g3b.y *= b; g3c.x *= b; g3c.y *= b;
        *reinterpret_cast<float2*>(row + 576 + 6 * lane)     = g3a;
        *reinterpret_cast<float2*>(row + 576 + 6 * lane + 2) = g3b;
        *reinterpret_cast<float2*>(row + 576 + 6 * lane + 4) = g3c;
    }
    {   // field4
        const float2 wv = *reinterpret_cast<const float2*>(lnw + 384 + 2 * lane);
        const float a = wv.x * r4, b = wv.y * r4;
        g4a.x *= a; g4a.y *= a; g4b.x *= a; g4b.y *= b; g4c.x *= b; g4c.y *= b;
        *reinterpret_cast<float2*>(row + 768 + 6 * lane)     = g4a;
        *reinterpret_cast<float2*>(row + 768 + 6 * lane + 2) = g4b;
        *reinterpret_cast<float2*>(row + 768 + 6 * lane + 4) = g4c;
    }
}

// ---------------------------------------------------------------------------
extern "C" void kernel_launch(void* const* d_in, const int* in_sizes, int n_in,
                              void* d_out, int out_size)
{
    const float* node_feat   = (const float*)d_in[0];
    const float* edge_sh     = (const float*)d_in[1];
    const float* edge_weight = (const float*)d_in[2];
    const float* tp_bias     = (const float*)d_in[3];
    const float* ln_weight   = (const float*)d_in[4];
    const float* ln_bias     = (const float*)d_in[5];
    const int*   edge_src    = (const int*)d_in[6];
    const int*   edge_dst    = (const int*)d_in[7];
    float* out = (float*)d_out;

    const int n_nodes = in_sizes[0] / 320;
    const int n_edges = in_sizes[7];

    // 1) zero accumulator (d_out is poisoned before timing)
    const int n4 = out_size / 4;
    zero_kernel<<<2048, 256>>>(reinterpret_cast<float4*>(out), n4);

    // 2) fused TP + bias + scatter-add (1 warp per edge)
    {
        const int warps_per_block = 256 / 32;
        const int blocks = (n_edges + warps_per_block - 1) / warps_per_block;
        tp_scatter_kernel<<<blocks, 256>>>(node_feat, edge_sh, edge_weight,
                                           tp_bias, edge_src, edge_dst,
                                           out, n_edges);
    }

    // 3) equivariant LayerNorm in place (1 warp per node)
    {
        const int warps_per_block = 256 / 32;
        const int blocks = (n_nodes + warps_per_block - 1) / warps_per_block;
        ln_kernel<<<blocks, 256>>>(out, ln_weight, ln_bias, n_nodes);
    }
}

// round 2
// speedup vs baseline: 1.7263x; 1.7263x over previous
#include <cuda_runtime.h>
#include <cuda_bf16.h>
#include <cstdint>

#define INV_SQRT3 0.57735026918962576451f
#define INV_SQRT2 0.70710678118654752440f
#define LN_EPS 1e-5f

#define MAX_NODES 16384
#define MAX_EDGES 131072

// scratch (allocation-free rule: __device__ globals)
__device__ int g_hist[MAX_NODES];
__device__ int g_cursor[MAX_NODES];
__device__ int g_start[MAX_NODES + 1];
__device__ int g_sorted[MAX_EDGES];

__device__ __forceinline__ float warp_sum(float v) {
    v += __shfl_xor_sync(0xffffffffu, v, 16);
    v += __shfl_xor_sync(0xffffffffu, v, 8);
    v += __shfl_xor_sync(0xffffffffu, v, 4);
    v += __shfl_xor_sync(0xffffffffu, v, 2);
    v += __shfl_xor_sync(0xffffffffu, v, 1);
    return v;
}

// ---------------------------------------------------------------------------
// Sort pipeline: counting sort of edge ids by edge_dst
// ---------------------------------------------------------------------------
__global__ void hist_zero_kernel(int n_nodes) {
    int i = blockIdx.x * blockDim.x + threadIdx.x;
    if (i < n_nodes) g_hist[i] = 0;
}

__global__ void hist_count_kernel(const int* __restrict__ edge_dst, int n_edges) {
    int i = blockIdx.x * blockDim.x + threadIdx.x;
    if (i < n_edges) atomicAdd(&g_hist[edge_dst[i]], 1);
}

// single block, 1024 threads, 16 bins per thread (covers 16384 nodes)
__global__ void __launch_bounds__(1024) scan_kernel(int n_nodes) {
    __shared__ int ssum[1024];
    const int t = threadIdx.x;
    const int base = t * 16;

    int v[16];
    int s = 0;
#pragma unroll
    for (int i = 0; i < 16; i++) {
        int idx = base + i;
        v[i] = (idx < n_nodes) ? g_hist[idx] : 0;
        s += v[i];
    }
    ssum[t] = s;
    __syncthreads();

    // Hillis-Steele inclusive scan over thread sums
    for (int off = 1; off < 1024; off <<= 1) {
        int x = (t >= off) ? ssum[t - off] : 0;
        __syncthreads();
        ssum[t] += x;
        __syncthreads();
    }

    int run = (t == 0) ? 0 : ssum[t - 1];  // exclusive base
#pragma unroll
    for (int i = 0; i < 16; i++) {
        int idx = base + i;
        if (idx < n_nodes) {
            g_start[idx] = run;
            g_cursor[idx] = run;
        }
        run += v[i];
    }
    if (t == 1023) g_start[n_nodes] = run;  // == n_edges
}

__global__ void scatter_kernel(const int* __restrict__ edge_dst, int n_edges) {
    int i = blockIdx.x * blockDim.x + threadIdx.x;
    if (i < n_edges) {
        int pos = atomicAdd(&g_cursor[edge_dst[i]], 1);
        g_sorted[pos] = i;
    }
}

// ---------------------------------------------------------------------------
// Fused: gather edges of node -> depthwise TP accumulate in registers
//        -> + deg*bias -> equivariant LayerNorm -> single store.
// One warp per node. Lane L owns scalar channels 4L..4L+3 and vector
// channels 2L, 2L+1.
//
// Row layout (960 floats):
//   [  0,128) out0a   [128,192) out0b   [192,576) out1a (u*3+d)
//   [576,768) out1b   [768,960) out1c
// ---------------------------------------------------------------------------
__global__ void __launch_bounds__(256) fused_tp_ln_kernel(
    const float* __restrict__ node_feat,   // (N, 320)
    const float* __restrict__ edge_sh,     // (E, 4)
    const float* __restrict__ edge_weight, // (E, 448)
    const float* __restrict__ tp_bias,     // (192,)
    const int*   __restrict__ edge_src,
    const float* __restrict__ lnw,         // (448,)
    const float* __restrict__ lnb,         // (192,)
    float*       __restrict__ out,         // (N, 960)
    int n_nodes)
{
    const int warp = (blockIdx.x * blockDim.x + threadIdx.x) >> 5;
    const int lane = threadIdx.x & 31;
    if (warp >= n_nodes) return;
    const int node = warp;

    const int beg = g_start[node];
    const int end = g_start[node + 1];
    const int deg = end - beg;

    // accumulators (30 floats / lane = full 960-float row across the warp)
    float a0x = 0.f, a0y = 0.f, a0z = 0.f, a0w = 0.f;  // out0a
    float ob0 = 0.f, ob1 = 0.f;                         // out0b
    float A[12];                                        // out1a
    float B[6];                                         // out1b
    float C[6];                                         // out1c
#pragma unroll
    for (int i = 0; i < 12; i++) A[i] = 0.f;
#pragma unroll
    for (int i = 0; i < 6; i++) { B[i] = 0.f; C[i] = 0.f; }

    for (int ei = beg; ei < end; ei++) {
        const int e = __ldg(g_sorted + ei);
        const int s = __ldg(edge_src + e);

        const float4 shv = __ldg(reinterpret_cast<const float4*>(edge_sh) + e);
        const float ys = shv.x, yv0 = shv.y, yv1 = shv.z, yv2 = shv.w;

        const float* xrow = node_feat + (size_t)s * 320u;
        const float* wrow = edge_weight + (size_t)e * 448u;

        // scalar channels
        const float4 xs = __ldg(reinterpret_cast<const float4*>(xrow + 4 * lane));
        const float4 w0 = __ldg(reinterpret_cast<const float4*>(wrow + 4 * lane));
        const float4 w1 = __ldg(reinterpret_cast<const float4*>(wrow + 128 + 4 * lane));

        a0x += w0.x * xs.x * ys;
        a0y += w0.y * xs.y * ys;
        a0z += w0.z * xs.z * ys;
        a0w += w0.w * xs.w * ys;

        const float t0 = w1.x * xs.x, t1 = w1.y * xs.y;
        const float t2 = w1.z * xs.z, t3 = w1.w * xs.w;
        A[0] += t0 * yv0; A[1]  += t0 * yv1; A[2]  += t0 * yv2;
        A[3] += t1 * yv0; A[4]  += t1 * yv1; A[5]  += t1 * yv2;
        A[6] += t2 * yv0; A[7]  += t2 * yv1; A[8]  += t2 * yv2;
        A[9] += t3 * yv0; A[10] += t3 * yv1; A[11] += t3 * yv2;

        // vector channels
        const float2 w2 = __ldg(reinterpret_cast<const float2*>(wrow + 256 + 2 * lane));
        const float2 w3 = __ldg(reinterpret_cast<const float2*>(wrow + 320 + 2 * lane));
        const float2 w4 = __ldg(reinterpret_cast<const float2*>(wrow + 384 + 2 * lane));

        const float2 p0 = __ldg(reinterpret_cast<const float2*>(xrow + 128 + 6 * lane));
        const float2 p1 = __ldg(reinterpret_cast<const float2*>(xrow + 128 + 6 * lane + 2));
        const float2 p2 = __ldg(reinterpret_cast<const float2*>(xrow + 128 + 6 * lane + 4));
        // xv[v0] = (p0.x, p0.y, p1.x) ; xv[v1] = (p1.y, p2.x, p2.y)

        // out0b
        const float d0 = p0.x * yv0 + p0.y * yv1 + p1.x * yv2;
        const float d1 = p1.y * yv0 + p2.x * yv1 + p2.y * yv2;
        ob0 += w3.x * d0 * INV_SQRT3;
        ob1 += w3.y * d1 * INV_SQRT3;

        // out1b
        const float c0 = w2.x * ys, c1 = w2.y * ys;
        B[0] += c0 * p0.x; B[1] += c0 * p0.y; B[2] += c0 * p1.x;
        B[3] += c1 * p1.y; B[4] += c1 * p2.x; B[5] += c1 * p2.y;

        // out1c: w4 * cross(xv, yv) / sqrt2
        const float k0 = w4.x * INV_SQRT2, k1 = w4.y * INV_SQRT2;
        C[0] += k0 * (p0.y * yv2 - p1.x * yv1);
        C[1] += k0 * (p1.x * yv0 - p0.x * yv2);
        C[2] += k0 * (p0.x * yv1 - p0.y * yv0);
        C[3] += k1 * (p2.x * yv2 - p2.y * yv1);
        C[4] += k1 * (p2.y * yv0 - p1.y * yv2);
        C[5] += k1 * (p1.y * yv1 - p2.x * yv0);
    }

    // per-edge bias, summed over deg edges
    const float fdeg = (float)deg;
    {
        const float4 b0 = __ldg(reinterpret_cast<const float4*>(tp_bias + 4 * lane));
        a0x += fdeg * b0.x; a0y += fdeg * b0.y;
        a0z += fdeg * b0.z; a0w += fdeg * b0.w;
        const float2 bb = __ldg(reinterpret_cast<const float2*>(tp_bias + 128 + 2 * lane));
        ob0 += fdeg * bb.x; ob1 += fdeg * bb.y;
    }

    // ---- equivariant LayerNorm on register-resident row ---------------------
    float s0 = a0x + a0y + a0z + a0w;
    float q0 = a0x * a0x + a0y * a0y + a0z * a0z + a0w * a0w;
    float s1 = ob0 + ob1;
    float q1 = ob0 * ob0 + ob1 * ob1;
    float q2 = 0.f, q3 = 0.f, q4 = 0.f;
#pragma unroll
    for (int i = 0; i < 12; i++) q2 += A[i] * A[i];
#pragma unroll
    for (int i = 0; i < 6; i++) { q3 += B[i] * B[i]; q4 += C[i] * C[i]; }

    s0 = warp_sum(s0); q0 = warp_sum(q0);
    s1 = warp_sum(s1); q1 = warp_sum(q1);
    q2 = warp_sum(q2); q3 = warp_sum(q3); q4 = warp_sum(q4);

    const float mu0 = s0 * (1.f / 128.f);
    const float r0  = rsqrtf(fmaxf(q0 * (1.f / 128.f) - mu0 * mu0, 0.f) + LN_EPS);
    const float mu1 = s1 * (1.f / 64.f);
    const float r1  = rsqrtf(fmaxf(q1 * (1.f / 64.f) - mu1 * mu1, 0.f) + LN_EPS);
    const float r2  = rsqrtf(q2 * (1.f / 384.f) + LN_EPS);
    const float r3  = rsqrtf(q3 * (1.f / 192.f) + LN_EPS);
    const float r4  = rsqrtf(q4 * (1.f / 192.f) + LN_EPS);

    float* row = out + (size_t)node * 960u;

    {   // field0
        const float4 wv = __ldg(reinterpret_cast<const float4*>(lnw + 4 * lane));
        const float4 bv = __ldg(reinterpret_cast<const float4*>(lnb + 4 * lane));
        float4 o;
        o.x = (a0x - mu0) * r0 * wv.x + bv.x;
        o.y = (a0y - mu0) * r0 * wv.y + bv.y;
        o.z = (a0z - mu0) * r0 * wv.z + bv.z;
        o.w = (a0w - mu0) * r0 * wv.w + bv.w;
        *reinterpret_cast<float4*>(row + 4 * lane) = o;
    }
    {   // field1
        const float2 wv = __ldg(reinterpret_cast<const float2*>(lnw + 128 + 2 * lane));
        const float2 bv = __ldg(reinterpret_cast<const float2*>(lnb + 128 + 2 * lane));
        float2 o;
        o.x = (ob0 - mu1) * r1 * wv.x + bv.x;
        o.y = (ob1 - mu1) * r1 * wv.y + bv.y;
        *reinterpret_cast<float2*>(row + 128 + 2 * lane) = o;
    }
    {   // field2: per-channel scale, channels u = 4*lane + {0..3}
        const float4 wv = __ldg(reinterpret_cast<const float4*>(lnw + 192 + 4 * lane));
        const float sa = wv.x * r2, sb = wv.y * r2, sc = wv.z * r2, sd = wv.w * r2;
        float4 o1 = make_float4(A[0] * sa, A[1] * sa, A[2]  * sa, A[3]  * sb);
        float4 o2 = make_float4(A[4] * sb, A[5] * sb, A[6]  * sc, A[7]  * sc);
        float4 o3 = make_float4(A[8] * sc, A[9] * sd, A[10] * sd, A[11] * sd);
        *reinterpret_cast<float4*>(row + 192 + 12 * lane)     = o1;
        *reinterpret_cast<float4*>(row + 192 + 12 * lane + 4) = o2;
        *reinterpret_cast<float4*>(row + 192 + 12 * lane + 8) = o3;
    }
    {   // field3
        const float2 wv = __ldg(reinterpret_cast<const float2*>(lnw + 320 + 2 * lane));
        const float sa = wv.x * r3, sb = wv.y * r3;
        float2 o1 = make_float2(B[0] * sa, B[1] * sa);
        float2 o2 = make_float2(B[2] * sa, B[3] * sb);
        float2 o3 = make_float2(B[4] * sb, B[5] * sb);
        *reinterpret_cast<float2*>(row + 576 + 6 * lane)     = o1;
        *reinterpret_cast<float2*>(row + 576 + 6 * lane + 2) = o2;
        *reinterpret_cast<float2*>(row + 576 + 6 * lane + 4) = o3;
    }
    {   // field4
        const float2 wv = __ldg(reinterpret_cast<const float2*>(lnw + 384 + 2 * lane));
        const float sa = wv.x * r4, sb = wv.y * r4;
        float2 o1 = make_float2(C[0] * sa, C[1] * sa);
        float2 o2 = make_float2(C[2] * sa, C[3] * sb);
        float2 o3 = make_float2(C[4] * sb, C[5] * sb);
        *reinterpret_cast<float2*>(row + 768 + 6 * lane)     = o1;
        *reinterpret_cast<float2*>(row + 768 + 6 * lane + 2) = o2;
        *reinterpret_cast<float2*>(row + 768 + 6 * lane + 4) = o3;
    }
}

// ---------------------------------------------------------------------------
extern "C" void kernel_launch(void* const* d_in, const int* in_sizes, int n_in,
                              void* d_out, int out_size)
{
    const float* node_feat   = (const float*)d_in[0];
    const float* edge_sh     = (const float*)d_in[1];
    const float* edge_weight = (const float*)d_in[2];
    const float* tp_bias     = (const float*)d_in[3];
    const float* ln_weight   = (const float*)d_in[4];
    const float* ln_bias     = (const float*)d_in[5];
    const int*   edge_src    = (const int*)d_in[6];
    const int*   edge_dst    = (const int*)d_in[7];
    float* out = (float*)d_out;

    const int n_nodes = in_sizes[0] / 320;
    const int n_edges = in_sizes[7];

    // counting sort of edges by dst
    hist_zero_kernel<<<(n_nodes + 255) / 256, 256>>>(n_nodes);
    hist_count_kernel<<<(n_edges + 255) / 256, 256>>>(edge_dst, n_edges);
    scan_kernel<<<1, 1024>>>(n_nodes);
    scatter_kernel<<<(n_edges + 255) / 256, 256>>>(edge_dst, n_edges);

    // fused TP + bias + aggregate + LN, warp per node
    const int warps_per_block = 256 / 32;
    const int blocks = (n_nodes + warps_per_block - 1) / warps_per_block;
    fused_tp_ln_kernel<<<blocks, 256>>>(node_feat, edge_sh, edge_weight,
                                        tp_bias, edge_src, ln_weight, ln_bias,
                                        out, n_nodes);
}